// round 2
// baseline (speedup 1.0000x reference)
#include <cuda_runtime.h>

// SSIM over (64,1,512,512) f32, 11x11 zero-padded box filters.
// Strategy: separable box filter.
//   1) Vertical running sums of (x, y, x^2, y^2, x*y): thread-per-column,
//      coalesced LDG; "old" row reloads hit L1 (11-row working set ~11KB/CTA).
//   2) Stage 16 rows of the 5 vertical sums in shared memory.
//   3) Horizontal 11-tap sliding sums + pointwise SSIM into a staging tile.
//   4) Coalesced store pass.

namespace {
constexpr int W = 512, H = 512;
constexpr int PAD = 5;                 // win=11 -> halo 5
constexpr int TX = 118;                // output cols per strip
constexpr int NSTRIP = 5;              // ceil(512/118)
constexpr int THREADS = 128;           // TX + 2*PAD
constexpr int RCHUNK = 16;             // rows staged in smem per iteration
constexpr int RBLOCK = 128;            // output rows per CTA
constexpr int PITCH = 129;             // smem pitch (conflict-free for hrow=tid&15, hch=tid>>4)
constexpr float INV_N = 1.0f / 121.0f;
constexpr float COV = 121.0f / 120.0f;
}

__device__ __forceinline__ float ld0(const float* __restrict__ p, int r, int gcol, bool cv) {
    if (cv && r >= 0 && r < H) return __ldg(p + r * W + gcol);
    return 0.0f;
}

__global__ __launch_bounds__(THREADS) void ssim_kernel(
    const float* __restrict__ img, const float* __restrict__ ref,
    const float* __restrict__ drange, float* __restrict__ out)
{
    __shared__ float vs[RCHUNK][5][PITCH];   // vertical sums, 5 quantities
    __shared__ float so[RCHUNK][TX];         // output staging tile

    const int tid   = threadIdx.x;
    const int strip = blockIdx.x;
    const int rb    = blockIdx.y;
    const int b     = blockIdx.z;

    const float* ip = img + (size_t)b * H * W;
    const float* rp = ref + (size_t)b * H * W;
    float*       op = out + (size_t)b * H * W;

    const float dr = __ldg(drange + b);
    const float C1 = (0.01f * dr) * (0.01f * dr);
    const float C2 = (0.03f * dr) * (0.03f * dr);

    const int  gcol = strip * TX + tid - PAD;       // column this thread streams
    const bool cv   = (gcol >= 0) && (gcol < W);

    const int r_start = rb * RBLOCK;

    // --- init vertical running sums: rows [r_start-5, r_start+5] ---
    float sx = 0.f, sy = 0.f, sxx = 0.f, syy = 0.f, sxy = 0.f;
    #pragma unroll
    for (int d = -PAD; d <= PAD; ++d) {
        float x = ld0(ip, r_start + d, gcol, cv);
        float y = ld0(rp, r_start + d, gcol, cv);
        sx += x; sy += y;
        sxx = fmaf(x, x, sxx);
        syy = fmaf(y, y, syy);
        sxy = fmaf(x, y, sxy);
    }

    const int hrow = tid & (RCHUNK - 1);   // 0..15
    const int hch  = tid >> 4;             // 0..7
    const int c0   = hch * 15;             // 8 chunks of 15 cover 120 >= 118

    for (int ck = 0; ck < RBLOCK / RCHUNK; ++ck) {
        const int r0 = r_start + ck * RCHUNK;

        // --- vertical stage: stage 16 rows of vertical sums ---
        #pragma unroll 4
        for (int i = 0; i < RCHUNK; ++i) {
            vs[i][0][tid] = sx;
            vs[i][1][tid] = sy;
            vs[i][2][tid] = sxx;
            vs[i][3][tid] = syy;
            vs[i][4][tid] = sxy;
            const int r = r0 + i;
            float xn = ld0(ip, r + PAD + 1, gcol, cv);
            float yn = ld0(rp, r + PAD + 1, gcol, cv);
            float xo = ld0(ip, r - PAD, gcol, cv);        // L1 hit (loaded 11 rows ago)
            float yo = ld0(rp, r - PAD, gcol, cv);
            sx += xn - xo;
            sy += yn - yo;
            sxx += xn * xn - xo * xo;
            syy += yn * yn - yo * yo;
            sxy += xn * yn - xo * yo;
        }
        __syncthreads();

        // --- horizontal sliding sums + SSIM math ---
        {
            float hx = 0.f, hy = 0.f, hxx = 0.f, hyy = 0.f, hxy = 0.f;
            #pragma unroll
            for (int j = 0; j < 11; ++j) {
                hx  += vs[hrow][0][c0 + j];
                hy  += vs[hrow][1][c0 + j];
                hxx += vs[hrow][2][c0 + j];
                hyy += vs[hrow][3][c0 + j];
                hxy += vs[hrow][4][c0 + j];
            }
            #pragma unroll
            for (int k = 0; k < 15; ++k) {
                const int c = c0 + k;
                if (c < TX) {
                    float ux  = hx  * INV_N;
                    float uy  = hy  * INV_N;
                    float uxx = hxx * INV_N;
                    float uyy = hyy * INV_N;
                    float uxy = hxy * INV_N;
                    float vx  = COV * (uxx - ux * ux);
                    float vy  = COV * (uyy - uy * uy);
                    float vxy = COV * (uxy - ux * uy);
                    float A1 = 2.f * ux * uy + C1;
                    float A2 = 2.f * vxy + C2;
                    float B1 = ux * ux + uy * uy + C1;
                    float B2 = vx + vy + C2;
                    so[hrow][c] = __fdividef(A1 * A2, B1 * B2);
                    // slide window (reads of column c+11 stay within PITCH)
                    hx  += vs[hrow][0][c + 11] - vs[hrow][0][c];
                    hy  += vs[hrow][1][c + 11] - vs[hrow][1][c];
                    hxx += vs[hrow][2][c + 11] - vs[hrow][2][c];
                    hyy += vs[hrow][3][c + 11] - vs[hrow][3][c];
                    hxy += vs[hrow][4][c + 11] - vs[hrow][4][c];
                }
            }
        }
        __syncthreads();

        // --- coalesced store pass ---
        for (int idx = tid; idx < RCHUNK * TX; idx += THREADS) {
            int rr = idx / TX;
            int cc = idx - rr * TX;
            int ocol = strip * TX + cc;
            if (ocol < W) op[(r0 + rr) * W + ocol] = so[rr][cc];
        }
        __syncthreads();
    }
}

extern "C" void kernel_launch(void* const* d_in, const int* in_sizes, int n_in,
                              void* d_out, int out_size) {
    const float* img = (const float*)d_in[0];
    const float* ref = (const float*)d_in[1];
    const float* dr  = (const float*)d_in[2];
    float* out = (float*)d_out;
    const int B = in_sizes[2];            // batch = data_range element count (64)
    dim3 grid(NSTRIP, H / RBLOCK, B);
    ssim_kernel<<<grid, THREADS>>>(img, ref, dr, out);
}

// round 4
// speedup vs baseline: 1.6151x; 1.6151x over previous
#include <cuda_runtime.h>

// SSIM over (64,1,512,512) f32, 11x11 zero-padded box filters.
// Separable box filter, R3 revision:
//   - RCHUNK=8 (smem 49KB -> 24.4KB), __launch_bounds__(128,6): 6 CTAs/SM.
//   - Vertical sums packed float4(sx,sy,sxx,syy) + float(sxy): 2 LDS / point
//     in the horizontal stage instead of 5.
//   - Conflict-free pitches: vs4/vs1 pitch 129, so pitch 119 (verified vs the
//     hrow=tid&7 / hch=tid>>3 lane mapping).
//   - Store pass: 8 plain coalesced row stores.

namespace {
constexpr int W = 512, H = 512;
constexpr int PAD = 5;                 // win=11 -> halo 5
constexpr int TX = 118;                // output cols per strip
constexpr int NSTRIP = 5;              // ceil(512/118)
constexpr int THREADS = 128;           // TX + 2*PAD
constexpr int RCHUNK = 8;              // rows staged in smem per iteration
constexpr int RBLOCK = 128;            // output rows per CTA
constexpr int PITCH = 129;             // vs pitch (floats/float4s per row)
constexpr int SO_PITCH = 119;          // staging pitch (odd, conflict-free)
constexpr float INV_N = 1.0f / 121.0f;
constexpr float COV = 121.0f / 120.0f;
}

__device__ __forceinline__ float ld0(const float* __restrict__ p, int r, int gcol, bool cv) {
    if (cv && r >= 0 && r < H) return __ldg(p + r * W + gcol);
    return 0.0f;
}

__global__ __launch_bounds__(THREADS, 6) void ssim_kernel(
    const float* __restrict__ img, const float* __restrict__ ref,
    const float* __restrict__ drange, float* __restrict__ out)
{
    __shared__ float4 vs4[RCHUNK][PITCH];    // (sx, sy, sxx, syy)
    __shared__ float  vs1[RCHUNK][PITCH];    // sxy
    __shared__ float  so[RCHUNK][SO_PITCH];  // output staging tile

    const int tid   = threadIdx.x;
    const int strip = blockIdx.x;
    const int rb    = blockIdx.y;
    const int b     = blockIdx.z;

    const float* ip = img + (size_t)b * H * W;
    const float* rp = ref + (size_t)b * H * W;
    float*       op = out + (size_t)b * H * W;

    const float dr = __ldg(drange + b);
    const float C1 = (0.01f * dr) * (0.01f * dr);
    const float C2 = (0.03f * dr) * (0.03f * dr);

    const int  gcol = strip * TX + tid - PAD;       // column this thread streams
    const bool cv   = (gcol >= 0) && (gcol < W);

    const int r_start = rb * RBLOCK;

    // --- init vertical running sums: rows [r_start-5, r_start+5] ---
    float sx = 0.f, sy = 0.f, sxx = 0.f, syy = 0.f, sxy = 0.f;
    #pragma unroll
    for (int d = -PAD; d <= PAD; ++d) {
        float x = ld0(ip, r_start + d, gcol, cv);
        float y = ld0(rp, r_start + d, gcol, cv);
        sx += x; sy += y;
        sxx = fmaf(x, x, sxx);
        syy = fmaf(y, y, syy);
        sxy = fmaf(x, y, sxy);
    }

    const int hrow = tid & (RCHUNK - 1);   // 0..7
    const int hch  = tid >> 3;             // 0..15
    const int c0   = hch * 8;              // 15 chunks of 8 cover 118 (hch=15 idle)
    const bool hact = (c0 < TX);

    for (int ck = 0; ck < RBLOCK / RCHUNK; ++ck) {
        const int r0 = r_start + ck * RCHUNK;

        // --- vertical stage: stage 8 rows of vertical sums (packed) ---
        #pragma unroll
        for (int i = 0; i < RCHUNK; ++i) {
            vs4[i][tid] = make_float4(sx, sy, sxx, syy);
            vs1[i][tid] = sxy;
            const int r = r0 + i;
            float xn = ld0(ip, r + PAD + 1, gcol, cv);
            float yn = ld0(rp, r + PAD + 1, gcol, cv);
            float xo = ld0(ip, r - PAD, gcol, cv);        // L1 hit (loaded 11 rows ago)
            float yo = ld0(rp, r - PAD, gcol, cv);
            sx += xn - xo;
            sy += yn - yo;
            sxx += xn * xn - xo * xo;
            syy += yn * yn - yo * yo;
            sxy += xn * yn - xo * yo;
        }
        __syncthreads();

        // --- horizontal sliding sums + SSIM math ---
        if (hact) {
            float hx = 0.f, hy = 0.f, hxx = 0.f, hyy = 0.f, hxy = 0.f;
            #pragma unroll
            for (int j = 0; j < 11; ++j) {
                float4 v = vs4[hrow][c0 + j];
                hx += v.x; hy += v.y; hxx += v.z; hyy += v.w;
                hxy += vs1[hrow][c0 + j];
            }
            #pragma unroll
            for (int k = 0; k < 8; ++k) {
                const int c = c0 + k;
                if (c < TX) {
                    float ux  = hx  * INV_N;
                    float uy  = hy  * INV_N;
                    float uxx = hxx * INV_N;
                    float uyy = hyy * INV_N;
                    float uxy = hxy * INV_N;
                    float vx  = COV * (uxx - ux * ux);
                    float vy  = COV * (uyy - uy * uy);
                    float vxy = COV * (uxy - ux * uy);
                    float A1 = 2.f * ux * uy + C1;
                    float A2 = 2.f * vxy + C2;
                    float B1 = ux * ux + uy * uy + C1;
                    float B2 = vx + vy + C2;
                    so[hrow][c] = __fdividef(A1 * A2, B1 * B2);
                    // slide window (index c+11 <= 128 < PITCH; safe)
                    float4 va = vs4[hrow][c + 11];
                    float4 vb = vs4[hrow][c];
                    hx  += va.x - vb.x;
                    hy  += va.y - vb.y;
                    hxx += va.z - vb.z;
                    hyy += va.w - vb.w;
                    hxy += vs1[hrow][c + 11] - vs1[hrow][c];
                }
            }
        }
        __syncthreads();

        // --- coalesced store pass: 8 rows, 118 lanes each ---
        if (tid < TX) {
            const int ocol = strip * TX + tid;
            if (ocol < W) {
                #pragma unroll
                for (int rr = 0; rr < RCHUNK; ++rr)
                    op[(r0 + rr) * W + ocol] = so[rr][tid];
            }
        }
        __syncthreads();
    }
}

extern "C" void kernel_launch(void* const* d_in, const int* in_sizes, int n_in,
                              void* d_out, int out_size) {
    const float* img = (const float*)d_in[0];
    const float* ref = (const float*)d_in[1];
    const float* dr  = (const float*)d_in[2];
    float* out = (float*)d_out;
    const int B = in_sizes[2];            // batch = data_range element count (64)
    dim3 grid(NSTRIP, H / RBLOCK, B);
    ssim_kernel<<<grid, THREADS>>>(img, ref, dr, out);
}

// round 5
// speedup vs baseline: 2.0265x; 1.2547x over previous
#include <cuda_runtime.h>

// SSIM over (64,1,512,512) f32, 11x11 zero-padded box filters.
// Separable box filter, R4 revision:
//   - Algebraic reduction: SSIM only needs vx+vy, so stage 4 quantities
//     (sx, sy, s(x^2+y^2), s(x*y)) as ONE float4 -> 20% less smem traffic,
//     smem 24.4KB -> 20.4KB, fewer registers.
//   - __launch_bounds__(128,7): 7 CTAs/SM (28 warps).
//   - RBLOCK=64 -> grid 2560: shorter, better-balanced wave tail.
//   - Last slide per chunk elided (k<7 guard).

namespace {
constexpr int W = 512, H = 512;
constexpr int PAD = 5;                 // win=11 -> halo 5
constexpr int TX = 118;                // output cols per strip
constexpr int NSTRIP = 5;              // ceil(512/118)
constexpr int THREADS = 128;           // TX + 2*PAD
constexpr int RCHUNK = 8;              // rows staged in smem per iteration
constexpr int RBLOCK = 64;             // output rows per CTA
constexpr int PITCH = 129;             // vs pitch (float4s per row), conflict-free
constexpr int SO_PITCH = 119;          // staging pitch (odd, conflict-free)
constexpr float INV_N = 1.0f / 121.0f;
constexpr float COV = 121.0f / 120.0f;
}

__device__ __forceinline__ float ld0(const float* __restrict__ p, int r, int gcol, bool cv) {
    if (cv && r >= 0 && r < H) return __ldg(p + r * W + gcol);
    return 0.0f;
}

__global__ __launch_bounds__(THREADS, 7) void ssim_kernel(
    const float* __restrict__ img, const float* __restrict__ ref,
    const float* __restrict__ drange, float* __restrict__ out)
{
    __shared__ float4 vs4[RCHUNK][PITCH];    // (sx, sy, s(xx+yy), sxy)
    __shared__ float  so[RCHUNK][SO_PITCH];  // output staging tile

    const int tid   = threadIdx.x;
    const int strip = blockIdx.x;
    const int rb    = blockIdx.y;
    const int b     = blockIdx.z;

    const float* ip = img + (size_t)b * H * W;
    const float* rp = ref + (size_t)b * H * W;
    float*       op = out + (size_t)b * H * W;

    const float dr = __ldg(drange + b);
    const float C1 = (0.01f * dr) * (0.01f * dr);
    const float C2 = (0.03f * dr) * (0.03f * dr);

    const int  gcol = strip * TX + tid - PAD;       // column this thread streams
    const bool cv   = (gcol >= 0) && (gcol < W);

    const int r_start = rb * RBLOCK;

    // --- init vertical running sums: rows [r_start-5, r_start+5] ---
    float sx = 0.f, sy = 0.f, sq = 0.f, sxy = 0.f;
    #pragma unroll
    for (int d = -PAD; d <= PAD; ++d) {
        float x = ld0(ip, r_start + d, gcol, cv);
        float y = ld0(rp, r_start + d, gcol, cv);
        sx += x; sy += y;
        sq  = fmaf(x, x, sq);
        sq  = fmaf(y, y, sq);
        sxy = fmaf(x, y, sxy);
    }

    const int hrow = tid & (RCHUNK - 1);   // 0..7
    const int hch  = tid >> 3;             // 0..15
    const int c0   = hch * 8;              // 15 chunks of 8 cover 118 (hch=15 idle)
    const bool hact = (c0 < TX);

    for (int ck = 0; ck < RBLOCK / RCHUNK; ++ck) {
        const int r0 = r_start + ck * RCHUNK;

        // --- vertical stage: stage 8 rows of packed vertical sums ---
        #pragma unroll
        for (int i = 0; i < RCHUNK; ++i) {
            vs4[i][tid] = make_float4(sx, sy, sq, sxy);
            const int r = r0 + i;
            float xn = ld0(ip, r + PAD + 1, gcol, cv);
            float yn = ld0(rp, r + PAD + 1, gcol, cv);
            float xo = ld0(ip, r - PAD, gcol, cv);        // L1/L2 hit (loaded 11 rows ago)
            float yo = ld0(rp, r - PAD, gcol, cv);
            sx += xn - xo;
            sy += yn - yo;
            sq  += (xn * xn + yn * yn) - (xo * xo + yo * yo);
            sxy += xn * yn - xo * yo;
        }
        __syncthreads();

        // --- horizontal sliding sums + SSIM math ---
        if (hact) {
            float hx = 0.f, hy = 0.f, hq = 0.f, hxy = 0.f;
            #pragma unroll
            for (int j = 0; j < 11; ++j) {
                float4 v = vs4[hrow][c0 + j];
                hx += v.x; hy += v.y; hq += v.z; hxy += v.w;
            }
            #pragma unroll
            for (int k = 0; k < 8; ++k) {
                const int c = c0 + k;
                if (c < TX) {
                    float ux  = hx  * INV_N;
                    float uy  = hy  * INV_N;
                    float uq  = hq  * INV_N;
                    float uxy = hxy * INV_N;
                    float uxux = ux * ux;
                    float uyuy = uy * uy;
                    float vxy = COV * (uxy - ux * uy);
                    float A1 = 2.f * ux * uy + C1;
                    float A2 = 2.f * vxy + C2;
                    float B1 = uxux + uyuy + C1;
                    float B2 = COV * (uq - uxux - uyuy) + C2;
                    so[hrow][c] = __fdividef(A1 * A2, B1 * B2);
                    if (k < 7) {    // last slide feeds nothing; also avoids idx 128
                        float4 va = vs4[hrow][c + 11];
                        float4 vb = vs4[hrow][c];
                        hx  += va.x - vb.x;
                        hy  += va.y - vb.y;
                        hq  += va.z - vb.z;
                        hxy += va.w - vb.w;
                    }
                }
            }
        }
        __syncthreads();

        // --- coalesced store pass: 8 rows, 118 lanes each ---
        if (tid < TX) {
            const int ocol = strip * TX + tid;
            if (ocol < W) {
                #pragma unroll
                for (int rr = 0; rr < RCHUNK; ++rr)
                    op[(r0 + rr) * W + ocol] = so[rr][tid];
            }
        }
        __syncthreads();
    }
}

extern "C" void kernel_launch(void* const* d_in, const int* in_sizes, int n_in,
                              void* d_out, int out_size) {
    const float* img = (const float*)d_in[0];
    const float* ref = (const float*)d_in[1];
    const float* dr  = (const float*)d_in[2];
    float* out = (float*)d_out;
    const int B = in_sizes[2];            // batch = data_range element count (64)
    dim3 grid(NSTRIP, H / RBLOCK, B);
    ssim_kernel<<<grid, THREADS>>>(img, ref, dr, out);
}